// round 6
// baseline (speedup 1.0000x reference)
#include <cuda_runtime.h>
#include <math.h>

#define TT    8192
#define HH    512
#define MM    4096
#define NENT  128
#define MAXD  600
#define NF    100
#define CAP   512

// ---------------- scratch ----------------
__device__ float2 g_emb[MAXD];
__device__ int    g_cnt[2 * NENT];      // zero at load; re-zeroed by k_pair tail
__device__ int    g_done;
__device__ float4 g_clist[NENT * CAP];
__device__ float4 g_dlist[NENT * CAP];

__device__ __forceinline__ int ldI(const void* p, int idx, int is64) {
    return is64 ? (int)((const long long*)p)[idx] : ((const int*)p)[idx];
}
__device__ __forceinline__ unsigned long long pk2(float x, float y) {
    unsigned long long r;
    asm("mov.b64 %0, {%1, %2};" : "=l"(r) : "f"(x), "f"(y));
    return r;
}
__device__ __forceinline__ void fma2(unsigned long long& d, unsigned long long a,
                                     unsigned long long b) {
    asm("fma.rn.f32x2 %0, %1, %2, %0;" : "+l"(d) : "l"(a), "l"(b));
}
__device__ __forceinline__ void upk2(unsigned long long v, float& lo, float& hi) {
    asm("mov.b64 {%0, %1}, %2;" : "=f"(lo), "=f"(hi) : "l"(v));
}
__device__ __forceinline__ float tanh_fast(float x) {
    float y;
    asm("tanh.approx.f32 %0, %1;" : "=f"(y) : "f"(x));
    return y;
}

// ---------------- K1: fused span-sum + GEMM + tanh + Ws dot + bin ----------------
// 256 blocks (BMM=32 mentions), 320 threads, 2 blocks/SM.
// kh=tid/160 (k half), t2=tid%160, rg=t2%8 -> rows 4rg..4rg+3, cg=t2/8 (0..19)
// cols c = cg + 20j, j<5. acc[i][j] = f32x2 over row-pair (4rg+2i, 4rg+2i+1), col c.
#define BMM  32
#define BKK  32
#define NTH  320
#define ATP  36                     // As float stride (144B, 16B-aligned)
#define WP2  101                    // Wt u64 stride
#define AS_F (BKK * ATP)            // 1152 floats per buffer
#define WT_U (BKK * WP2)            // 3232 u64
#define POOLF (2 * AS_F + 2 * WT_U) // floats: 2304 + 6464*... (u64=2f) -> 8768

__global__ __launch_bounds__(NTH, 2) void k_mention(
        const float* __restrict__ h,
        const void* __restrict__ csp, const void* __restrict__ cent,
        const void* __restrict__ dsp, const void* __restrict__ dent,
        const float* __restrict__ Wc, const float* __restrict__ bc,
        const float* __restrict__ Wd, const float* __restrict__ bd,
        const float* __restrict__ Ws,
        const float* __restrict__ Wemb) {
    __shared__ __align__(16) float pool[POOLF];
    __shared__ int ss[BMM], se[BMM], sent[BMM];
    __shared__ int s_is64;

    float* As0 = pool;
    float* As1 = pool + AS_F;
    unsigned long long* Wt = (unsigned long long*)(pool + 2 * AS_F);  // single-buffered

    int tid = threadIdx.x;
    int m0 = blockIdx.x * BMM;
    bool isC = (m0 < MM);
    const float* W  = isC ? Wc : Wd;
    const float* bb = isC ? bc : bd;
    int wsb = isC ? 0 : NF;

    if (tid < 32) {
        unsigned v = (unsigned)((const int*)csp)[1 + 2 * tid];
        unsigned any = __ballot_sync(0xffffffffu, v != 0u);
        if (tid == 0) s_is64 = (any == 0u) ? 1 : 0;
    }
    __syncthreads();
    int is64 = s_is64;
    if (tid < BMM) {
        int mi = (m0 + tid) - (isC ? 0 : MM);
        const void* sp = isC ? csp : dsp;
        const void* en = isC ? cent : dent;
        ss[tid]   = ldI(sp, 2 * mi, is64);
        se[tid]   = ldI(sp, 2 * mi + 1, is64);
        sent[tid] = ldI(en, mi, is64);
    }
    __syncthreads();

    int kh = tid / 160;
    int t2 = tid - kh * 160;
    int rg = t2 & 7;             // rows 4rg + i
    int cg = t2 >> 3;            // 0..19
    int kh16 = kh * 16;

    // A task: 256 tasks (tid<256): r = tid>>3, q = tid&7
    const float4* __restrict__ hp = (const float4*)h;
    bool hasA = (tid < BMM * 8);
    int r0 = (tid >> 3) & (BMM - 1), q0 = tid & 7;
    int n0 = se[r0] - ss[r0];
    const float4* p0 = hp + (size_t)ss[r0] * (HH / 4) + q0;

    // W tasks: 5 float2 per thread
    int wg_off[5], ws_off[5];
    #pragma unroll
    for (int p = 0; p < 5; p++) {
        int i = tid + NTH * p;
        int kk = i / 50, c2 = i - kk * 50;
        wg_off[p] = kk * NF + 2 * c2;       // gmem float offset (per tile add kbase*NF)
        ws_off[p] = kk * WP2 + 2 * c2;      // smem u64 offset
    }

    unsigned long long acc[2][5];
    #pragma unroll
    for (int i = 0; i < 2; i++)
        #pragma unroll
        for (int j = 0; j < 5; j++) acc[i][j] = 0ull;

    float4 v0[8];
    float2 wr[5];

    // prologue: tile 0 loads (span loads predicated: no traffic for t>n)
    if (hasA) {
        v0[0] = __ldg(p0);
        #pragma unroll
        for (int t = 1; t < 8; t++)
            if (t <= n0) v0[t] = __ldg(p0 + (size_t)t * (HH / 4));
    }
    #pragma unroll
    for (int p = 0; p < 5; p++) wr[p] = __ldg((const float2*)&W[wg_off[p]]);

    for (int tile = 0; tile < HH / BKK; tile++) {
        float* Asb = (tile & 1) ? As1 : As0;
        // ---- commit prefetched regs -> smem ----
        if (hasA) {
            float4 a = v0[0];
            #pragma unroll
            for (int t = 1; t < 8; t++)
                if (t <= n0) { a.x += v0[t].x; a.y += v0[t].y; a.z += v0[t].z; a.w += v0[t].w; }
            float* dst = &Asb[(4 * q0 + 0) * ATP + 0];
            Asb[(4 * q0 + 0) * ATP + r0] = a.x;   // transposed: As[k][row]
            Asb[(4 * q0 + 1) * ATP + r0] = a.y;
            Asb[(4 * q0 + 2) * ATP + r0] = a.z;
            Asb[(4 * q0 + 3) * ATP + r0] = a.w;
            (void)dst;
        }
        #pragma unroll
        for (int p = 0; p < 5; p++) {            // duplicated W: (w,w) u64
            Wt[ws_off[p]]     = pk2(wr[p].x, wr[p].x);
            Wt[ws_off[p] + 1] = pk2(wr[p].y, wr[p].y);
        }
        __syncthreads();
        // ---- issue next tile's loads ----
        if (tile + 1 < HH / BKK) {
            int off = (tile + 1) * (BKK / 4);
            if (hasA) {
                v0[0] = __ldg(p0 + off);
                #pragma unroll
                for (int t = 1; t < 8; t++)
                    if (t <= n0) v0[t] = __ldg(p0 + off + (size_t)t * (HH / 4));
            }
            int kb = (tile + 1) * BKK * NF;
            #pragma unroll
            for (int p = 0; p < 5; p++)
                wr[p] = __ldg((const float2*)&W[kb + wg_off[p]]);
        }
        // ---- compute: 16 kk x (1 LDS.128 + 5 LDS.64 + 10 FFMA2) ----
        #pragma unroll
        for (int kki = 0; kki < 16; kki++) {
            int kk = kh16 + kki;
            ulonglong2 av = *(const ulonglong2*)&Asb[kk * ATP + 4 * rg]; // rows 4rg..+3
            #pragma unroll
            for (int j = 0; j < 5; j++) {
                unsigned long long w2 = Wt[kk * WP2 + (cg + 20 * j)];
                fma2(acc[0][j], av.x, w2);
                fma2(acc[1][j], av.y, w2);
            }
        }
        __syncthreads();   // protects Wt (single-buffered) + As WAR
    }

    // ---- merge k-halves + epilogue (alias pool; all tile reads done) ----
    float* red  = pool;                 // [100][34]: red[c*34 + row], row-pairs via u64
    float* red2 = pool + 100 * 34;      // [32][20][2]

    if (kh == 0) {
        #pragma unroll
        for (int j = 0; j < 5; j++) {
            int c = cg + 20 * j;
            *(unsigned long long*)&red[c * 34 + 4 * rg]     = acc[0][j];
            *(unsigned long long*)&red[c * 34 + 4 * rg + 2] = acc[1][j];
        }
    }
    __syncthreads();
    if (kh == 1) {
        float s0[4] = {0.f, 0.f, 0.f, 0.f}, s1[4] = {0.f, 0.f, 0.f, 0.f};
        #pragma unroll
        for (int j = 0; j < 5; j++) {
            int c = cg + 20 * j;
            float o0, o1, o2, o3, x0, x1, x2, x3;
            upk2(*(const unsigned long long*)&red[c * 34 + 4 * rg], o0, o1);
            upk2(*(const unsigned long long*)&red[c * 34 + 4 * rg + 2], o2, o3);
            upk2(acc[0][j], x0, x1);
            upk2(acc[1][j], x2, x3);
            float bias = bb[c];
            float2 w = *(const float2*)&Ws[(wsb + c) * 2];
            float t0 = tanh_fast(x0 + o0 + bias);
            float t1 = tanh_fast(x1 + o1 + bias);
            float t2v = tanh_fast(x2 + o2 + bias);
            float t3 = tanh_fast(x3 + o3 + bias);
            s0[0] += t0 * w.x;  s1[0] += t0 * w.y;
            s0[1] += t1 * w.x;  s1[1] += t1 * w.y;
            s0[2] += t2v * w.x; s1[2] += t2v * w.y;
            s0[3] += t3 * w.x;  s1[3] += t3 * w.y;
        }
        #pragma unroll
        for (int i = 0; i < 4; i++) {
            int row = 4 * rg + i;
            red2[(row * 20 + cg) * 2 + 0] = s0[i];
            red2[(row * 20 + cg) * 2 + 1] = s1[i];
        }
    }
    __syncthreads();
    if (tid < BMM) {
        float s0 = 0.f, s1 = 0.f;
        #pragma unroll
        for (int c = 0; c < 20; c++) {
            s0 += red2[(tid * 20 + c) * 2 + 0];
            s1 += red2[(tid * 20 + c) * 2 + 1];
        }
        int ent = sent[tid];
        int pos = atomicAdd(&g_cnt[(isC ? 0 : NENT) + ent], 1);
        if (pos < CAP) {
            float4 rec;
            rec.x = __int_as_float(ss[tid]);
            rec.y = s0; rec.z = s1; rec.w = 0.f;
            (isC ? g_clist : g_dlist)[ent * CAP + pos] = rec;
        }
    }

    // blocks 0..7: emb precontract (consumed only by k_pair)
    if (blockIdx.x < 8) {
        for (int i = tid; i < 75 * 2; i += NTH) {
            int d = 75 * blockIdx.x + (i >> 1), k = i & 1;
            float a = 0.f;
            #pragma unroll
            for (int j = 0; j < 50; j++)
                a += Wemb[d * 50 + j] * Ws[(200 + j) * 2 + k];
            if (k == 0) g_emb[d].x = a; else g_emb[d].y = a;
        }
    }
}

// ---------------- K2: pairwise max per entity pair + fused softmax ----------------
__global__ __launch_bounds__(256) void k_pair(const float* __restrict__ bs,
                                              float* __restrict__ out) {
    __shared__ float2 s_emb[MAXD];
    __shared__ float4 s_rec[16][32];    // .x=ds bits, .y/.z = score pair
    int ce = blockIdx.x;
    int dg = blockIdx.y;
    int tid = threadIdx.x;
    for (int i = tid; i < MAXD; i += 256) s_emb[i] = g_emb[i];
    for (int i = tid; i < 16 * 32; i += 256) {
        int dd = i >> 5, slot = i & 31;
        s_rec[dd][slot] = g_dlist[(dg * 16 + dd) * CAP + slot];
    }
    __syncthreads();

    int lane = tid & 31, w = tid >> 5;
    int nc = min(g_cnt[ce], CAP);
    float bs0 = __ldg(&bs[0]), bs1 = __ldg(&bs[1]);

    for (int dit = 0; dit < 2; dit++) {
        int dd = dit * 8 + w;
        int de = dg * 16 + dd;
        int nd = min(g_cnt[NENT + de], CAP);
        int nds = min(nd, 32);
        float m0 = -INFINITY, m1 = -INFINITY;

        for (int c0 = 0; c0 < nc; c0 += 32) {
            int ci = c0 + lane;
            float4 cr = (ci < nc) ? g_clist[ce * CAP + ci]
                                  : make_float4(0.f, -INFINITY, -INFINITY, 0.f);
            unsigned cs = (unsigned)__float_as_int(cr.x);
            float mA0 = -INFINITY, mA1 = -INFINITY;     // dual accumulators:
            float mB0 = -INFINITY, mB1 = -INFINITY;     // break the fmax chain
            int j = 0;
            #pragma unroll 2
            for (; j + 1 < nds; j += 2) {
                float4 ra = s_rec[dd][j];               // one uniform LDS.128
                float4 rb = s_rec[dd][j + 1];
                int da = min(__usad(cs, (unsigned)__float_as_int(ra.x), 0u),
                             (unsigned)(MAXD - 1));
                int db = min(__usad(cs, (unsigned)__float_as_int(rb.x), 0u),
                             (unsigned)(MAXD - 1));
                float2 ea = s_emb[da];
                float2 eb = s_emb[db];
                mA0 = fmaxf(mA0, ra.y + ea.x);
                mA1 = fmaxf(mA1, ra.z + ea.y);
                mB0 = fmaxf(mB0, rb.y + eb.x);
                mB1 = fmaxf(mB1, rb.z + eb.y);
            }
            if (j < nds) {
                float4 ra = s_rec[dd][j];
                int da = min(__usad(cs, (unsigned)__float_as_int(ra.x), 0u),
                             (unsigned)(MAXD - 1));
                float2 ea = s_emb[da];
                mA0 = fmaxf(mA0, ra.y + ea.x);
                mA1 = fmaxf(mA1, ra.z + ea.y);
            }
            m0 = fmaxf(m0, cr.y + fmaxf(mA0, mB0));
            m1 = fmaxf(m1, cr.z + fmaxf(mA1, mB1));
            for (int jj = 32; jj < nd; jj++) {          // safety tail
                float4 dr = g_dlist[de * CAP + jj];
                int d = min(__usad(cs, (unsigned)__float_as_int(dr.x), 0u),
                            (unsigned)(MAXD - 1));
                float2 ev = s_emb[d];
                m0 = fmaxf(m0, cr.y + dr.y + ev.x);
                m1 = fmaxf(m1, cr.z + dr.z + ev.y);
            }
        }
        #pragma unroll
        for (int off = 16; off > 0; off >>= 1) {
            m0 = fmaxf(m0, __shfl_xor_sync(0xffffffffu, m0, off));
            m1 = fmaxf(m1, __shfl_xor_sync(0xffffffffu, m1, off));
        }
        if (lane == 0) {
            float x0 = m0 + bs0, x1 = m1 + bs1;
            float mx = fmaxf(x0, x1);
            float e0 = expf(x0 - mx), e1 = expf(x1 - mx);
            float inv = 1.f / (e0 + e1);
            out[(ce * NENT + de) * 2 + 0] = e0 * inv;
            out[(ce * NENT + de) * 2 + 1] = e1 * inv;
        }
    }

    // ticket: last block re-zeroes g_cnt (+g_done) for next replay
    __threadfence();
    __syncthreads();
    if (tid == 0) {
        int old = atomicAdd(&g_done, 1);
        if (old == NENT * 8 - 1) {
            #pragma unroll 1
            for (int i = 0; i < 2 * NENT; i++) g_cnt[i] = 0;
            g_done = 0;
            __threadfence();
        }
    }
}

// ---------------- launch ----------------
extern "C" void kernel_launch(void* const* d_in, const int* in_sizes, int n_in,
                              void* d_out, int out_size) {
    const float* h    = (const float*)d_in[0];
    const void*  csp  = d_in[1];
    const void*  cent = d_in[2];
    const void*  dsp  = d_in[3];
    const void*  dent = d_in[4];
    const float* Wc   = (const float*)d_in[5];
    const float* bc   = (const float*)d_in[6];
    const float* Wd   = (const float*)d_in[7];
    const float* bd   = (const float*)d_in[8];
    const float* Wemb = (const float*)d_in[9];
    const float* Ws   = (const float*)d_in[10];
    const float* bs   = (const float*)d_in[11];
    float* out = (float*)d_out;

    k_mention<<<2 * MM / BMM, NTH>>>(h, csp, cent, dsp, dent, Wc, bc, Wd, bd, Ws, Wemb);
    k_pair<<<dim3(NENT, 8), 256>>>(bs, out);
}

// round 7
// speedup vs baseline: 1.4003x; 1.4003x over previous
#include <cuda_runtime.h>
#include <math.h>

#define TT    8192
#define HH    512
#define MM    4096
#define NENT  128
#define MAXD  600
#define NF    100
#define CAP   512

// ---------------- scratch ----------------
__device__ float2 g_emb[MAXD];
__device__ int    g_cnt[2 * NENT];      // zero at load; re-zeroed by k_pair tail
__device__ int    g_done;
__device__ float4 g_clist[NENT * CAP];
__device__ float4 g_dlist[NENT * CAP];

__device__ __forceinline__ int ldI(const void* p, int idx, int is64) {
    return is64 ? (int)((const long long*)p)[idx] : ((const int*)p)[idx];
}
__device__ __forceinline__ void fma2(unsigned long long& d, unsigned long long a,
                                     unsigned long long b) {
    asm("fma.rn.f32x2 %0, %1, %2, %0;" : "+l"(d) : "l"(a), "l"(b));
}
__device__ __forceinline__ void upk2(unsigned long long v, float& lo, float& hi) {
    asm("mov.b64 {%0, %1}, %2;" : "=f"(lo), "=f"(hi) : "l"(v));
}
__device__ __forceinline__ float tanh_fast(float x) {
    float y;
    asm("tanh.approx.f32 %0, %1;" : "=f"(y) : "f"(x));
    return y;
}

// ---------------- K1: fused span-sum + GEMM + tanh + Ws dot + bin ----------------
// 128 blocks (BMM=64), 320 threads. kh = tid/160, t2 = tid%160,
// rg = t2%16 -> rows rg+16i (i<4), cg = t2/16 (0..9) -> col pairs p = cg+10j (j<5).
// A stored transposed + DUPLICATED: Asd[kk][2r]=Asd[kk][2r+1]=a(r,kk) -> dup-a LDS.64
// feeds FFMA2 directly (no pack MOVs); addresses 8B-consecutive over rg: conflict-free.
#define BMM  64
#define BKK  32
#define NTH  320
#define ADP  130                    // Asd float stride per kk (dup layout)
#define WPAD 104                    // Wt float stride per kk (natural pairs)
#define AS_F (BKK * ADP)            // 4160 floats
#define WT_F (BKK * WPAD)           // 3328 floats
#define EPI_F (64 * 50 * 2 + 64 * 10 * 2)   // 7680 floats (epilogue alias)
#define POOLF (AS_F + WT_F > EPI_F ? AS_F + WT_F : EPI_F)

__global__ __launch_bounds__(NTH, 1) void k_mention(
        const float* __restrict__ h,
        const void* __restrict__ csp, const void* __restrict__ cent,
        const void* __restrict__ dsp, const void* __restrict__ dent,
        const float* __restrict__ Wc, const float* __restrict__ bc,
        const float* __restrict__ Wd, const float* __restrict__ bd,
        const float* __restrict__ Ws,
        const float* __restrict__ Wemb) {
    __shared__ __align__(16) float pool[POOLF];
    __shared__ int ss[BMM], se[BMM], sent[BMM];
    __shared__ int s_is64;

    float* Asd = pool;               // single-buffered
    float* Wt  = pool + AS_F;

    int tid = threadIdx.x;
    int m0 = blockIdx.x * BMM;
    bool isC = (m0 < MM);
    const float* W  = isC ? Wc : Wd;
    const float* bb = isC ? bc : bd;
    int wsb = isC ? 0 : NF;

    if (tid < 32) {
        unsigned v = (unsigned)((const int*)csp)[1 + 2 * tid];
        unsigned any = __ballot_sync(0xffffffffu, v != 0u);
        if (tid == 0) s_is64 = (any == 0u) ? 1 : 0;
    }
    __syncthreads();
    int is64 = s_is64;
    if (tid < BMM) {
        int mi = (m0 + tid) - (isC ? 0 : MM);
        const void* sp = isC ? csp : dsp;
        const void* en = isC ? cent : dent;
        ss[tid]   = ldI(sp, 2 * mi, is64);
        se[tid]   = ldI(sp, 2 * mi + 1, is64);
        sent[tid] = ldI(en, mi, is64);
    }
    __syncthreads();

    int kh = tid / 160;
    int t2 = tid - kh * 160;
    int rg = t2 & 15;            // rows rg + 16i
    int cg = t2 >> 4;            // 0..9
    int kh16 = kh * 16;

    // ---- hoisted A tasks (task0: all threads; task1: tid<192) ----
    const float4* __restrict__ hp = (const float4*)h;
    int r0 = tid >> 3, q0 = tid & 7;
    int n0 = se[r0] - ss[r0];
    const float4* p0 = hp + (size_t)ss[r0] * (HH / 4) + q0;
    int i1 = tid + NTH;
    bool has1 = (i1 < BMM * 8);
    int r1 = has1 ? (i1 >> 3) : 0, q1 = has1 ? (i1 & 7) : 0;
    int n1 = se[r1] - ss[r1];
    const float4* p1 = hp + (size_t)ss[r1] * (HH / 4) + q1;

    // ---- hoisted W tasks (5 float2 per thread) ----
    int kkp[5], c2p[5];
    #pragma unroll
    for (int p = 0; p < 5; p++) {
        int i = tid + NTH * p;
        kkp[p] = i / 50;
        c2p[p] = i - kkp[p] * 50;
    }

    unsigned long long acc[4][5];
    #pragma unroll
    for (int i = 0; i < 4; i++)
        #pragma unroll
        for (int j = 0; j < 5; j++) acc[i][j] = 0ull;

    float4 v0[8], v1[8];
    float2 wr[5];

    // prologue: issue loads for tile 0
    #pragma unroll
    for (int t = 0; t < 8; t++) v0[t] = __ldg(p0 + (size_t)min(t, n0) * (HH / 4));
    if (has1) {
        #pragma unroll
        for (int t = 0; t < 8; t++) v1[t] = __ldg(p1 + (size_t)min(t, n1) * (HH / 4));
    }
    #pragma unroll
    for (int p = 0; p < 5; p++)
        wr[p] = __ldg((const float2*)&W[(size_t)kkp[p] * NF + 2 * c2p[p]]);

    for (int tile = 0; tile < HH / BKK; tile++) {
        // ---- commit prefetched regs -> smem (duplicated A) ----
        {
            float4 a = v0[0];
            #pragma unroll
            for (int t = 1; t < 8; t++)
                if (t <= n0) { a.x += v0[t].x; a.y += v0[t].y; a.z += v0[t].z; a.w += v0[t].w; }
            *(float2*)&Asd[(4 * q0 + 0) * ADP + 2 * r0] = make_float2(a.x, a.x);
            *(float2*)&Asd[(4 * q0 + 1) * ADP + 2 * r0] = make_float2(a.y, a.y);
            *(float2*)&Asd[(4 * q0 + 2) * ADP + 2 * r0] = make_float2(a.z, a.z);
            *(float2*)&Asd[(4 * q0 + 3) * ADP + 2 * r0] = make_float2(a.w, a.w);
            if (has1) {
                float4 b = v1[0];
                #pragma unroll
                for (int t = 1; t < 8; t++)
                    if (t <= n1) { b.x += v1[t].x; b.y += v1[t].y; b.z += v1[t].z; b.w += v1[t].w; }
                *(float2*)&Asd[(4 * q1 + 0) * ADP + 2 * r1] = make_float2(b.x, b.x);
                *(float2*)&Asd[(4 * q1 + 1) * ADP + 2 * r1] = make_float2(b.y, b.y);
                *(float2*)&Asd[(4 * q1 + 2) * ADP + 2 * r1] = make_float2(b.z, b.z);
                *(float2*)&Asd[(4 * q1 + 3) * ADP + 2 * r1] = make_float2(b.w, b.w);
            }
            #pragma unroll
            for (int p = 0; p < 5; p++)
                *(float2*)&Wt[kkp[p] * WPAD + 2 * c2p[p]] = wr[p];
        }
        __syncthreads();
        // ---- issue next tile's loads (in flight during compute) ----
        if (tile + 1 < HH / BKK) {
            int off = (tile + 1) * (BKK / 4);
            v0[0] = __ldg(p0 + off);
            #pragma unroll
            for (int t = 1; t < 8; t++)
                if (t <= n0) v0[t] = __ldg(p0 + off + (size_t)t * (HH / 4));
            if (has1) {
                v1[0] = __ldg(p1 + off);
                #pragma unroll
                for (int t = 1; t < 8; t++)
                    if (t <= n1) v1[t] = __ldg(p1 + off + (size_t)t * (HH / 4));
            }
            int kb = (tile + 1) * BKK * NF;
            #pragma unroll
            for (int p = 0; p < 5; p++)
                wr[p] = __ldg((const float2*)&W[kb + (size_t)kkp[p] * NF + 2 * c2p[p]]);
        }
        // ---- compute: 16 kk x (4 LDS.64 dup-a + 5 LDS.64 w + 20 FFMA2) ----
        #pragma unroll
        for (int kki = 0; kki < 16; kki++) {
            int kk = kh16 + kki;
            const float* ab = &Asd[kk * ADP + 2 * rg];
            unsigned long long a0 = *(const unsigned long long*)(ab);
            unsigned long long a1 = *(const unsigned long long*)(ab + 32);
            unsigned long long a2 = *(const unsigned long long*)(ab + 64);
            unsigned long long a3 = *(const unsigned long long*)(ab + 96);
            #pragma unroll
            for (int j = 0; j < 5; j++) {
                unsigned long long w2 =
                    *(const unsigned long long*)&Wt[kk * WPAD + 2 * (cg + 10 * j)];
                fma2(acc[0][j], a0, w2);
                fma2(acc[1][j], a1, w2);
                fma2(acc[2][j], a2, w2);
                fma2(acc[3][j], a3, w2);
            }
        }
        __syncthreads();   // WAR: next commit overwrites Asd/Wt
    }

    // ---- merge k-halves + epilogue (alias pool) ----
    float2* red  = (float2*)pool;          // [64][50]
    float*  red2 = pool + 2 * 64 * 50;     // [64][10][2]

    if (kh == 0) {
        #pragma unroll
        for (int i = 0; i < 4; i++)
            #pragma unroll
            for (int j = 0; j < 5; j++) {
                float lo, hi;
                upk2(acc[i][j], lo, hi);
                red[(rg + 16 * i) * 50 + (cg + 10 * j)] = make_float2(lo, hi);
            }
    }
    __syncthreads();
    if (kh == 1) {
        float s0[4] = {0.f, 0.f, 0.f, 0.f}, s1[4] = {0.f, 0.f, 0.f, 0.f};
        #pragma unroll
        for (int j = 0; j < 5; j++) {
            int p = cg + 10 * j, c0 = 2 * p;
            float2 bias = *(const float2*)&bb[c0];
            float2 w0 = *(const float2*)&Ws[(wsb + c0) * 2];
            float2 w1 = *(const float2*)&Ws[(wsb + c0 + 1) * 2];
            #pragma unroll
            for (int i = 0; i < 4; i++) {
                float lo, hi;
                upk2(acc[i][j], lo, hi);
                float2 o = red[(rg + 16 * i) * 50 + p];
                float t0 = tanh_fast(lo + o.x + bias.x);
                float t1 = tanh_fast(hi + o.y + bias.y);
                s0[i] += t0 * w0.x + t1 * w1.x;
                s1[i] += t0 * w0.y + t1 * w1.y;
            }
        }
        #pragma unroll
        for (int i = 0; i < 4; i++) {
            int r = rg + 16 * i;
            red2[(r * 10 + cg) * 2 + 0] = s0[i];
            red2[(r * 10 + cg) * 2 + 1] = s1[i];
        }
    }
    __syncthreads();
    if (tid < BMM) {
        float s0 = 0.f, s1 = 0.f;
        #pragma unroll
        for (int c = 0; c < 10; c++) {
            s0 += red2[(tid * 10 + c) * 2 + 0];
            s1 += red2[(tid * 10 + c) * 2 + 1];
        }
        int ent = sent[tid];
        int pos = atomicAdd(&g_cnt[(isC ? 0 : NENT) + ent], 1);
        if (pos < CAP) {
            float4 rec;
            rec.x = __int_as_float(ss[tid]);
            rec.y = s0; rec.z = s1; rec.w = 0.f;
            (isC ? g_clist : g_dlist)[ent * CAP + pos] = rec;
        }
    }

    // blocks 0..7: emb precontract (consumed only by k_pair)
    if (blockIdx.x < 8) {
        for (int i = tid; i < 75 * 2; i += NTH) {
            int d = 75 * blockIdx.x + (i >> 1), k = i & 1;
            float a = 0.f;
            #pragma unroll
            for (int j = 0; j < 50; j++)
                a += Wemb[d * 50 + j] * Ws[(200 + j) * 2 + k];
            if (k == 0) g_emb[d].x = a; else g_emb[d].y = a;
        }
    }
}

// ---------------- K2: pairwise max per entity pair + fused softmax (round-4) ------
__global__ __launch_bounds__(256) void k_pair(const float* __restrict__ bs,
                                              float* __restrict__ out) {
    __shared__ float2 s_emb[MAXD];
    __shared__ int    s_ds[16][32];
    __shared__ float2 s_dyz[16][32];
    int ce = blockIdx.x;
    int dg = blockIdx.y;
    int tid = threadIdx.x;
    for (int i = tid; i < MAXD; i += 256) s_emb[i] = g_emb[i];
    for (int i = tid; i < 16 * 32; i += 256) {
        int dd = i >> 5, slot = i & 31;
        float4 r = g_dlist[(dg * 16 + dd) * CAP + slot];
        s_ds[dd][slot]  = __float_as_int(r.x);
        s_dyz[dd][slot] = make_float2(r.y, r.z);
    }
    __syncthreads();

    int lane = tid & 31, w = tid >> 5;
    int nc = min(g_cnt[ce], CAP);
    float bs0 = __ldg(&bs[0]), bs1 = __ldg(&bs[1]);

    for (int dit = 0; dit < 2; dit++) {
        int dd = dit * 8 + w;
        int de = dg * 16 + dd;
        int nd = min(g_cnt[NENT + de], CAP);
        int nds = min(nd, 32);
        float m0 = -INFINITY, m1 = -INFINITY;

        for (int c0 = 0; c0 < nc; c0 += 32) {
            int ci = c0 + lane;
            float4 cr = (ci < nc) ? g_clist[ce * CAP + ci]
                                  : make_float4(0.f, -INFINITY, -INFINITY, 0.f);
            int cs = __float_as_int(cr.x);
            float mm0 = -INFINITY, mm1 = -INFINITY;
            #pragma unroll 4
            for (int j = 0; j < nds; j++) {
                int d = min(__usad((unsigned)cs, (unsigned)s_ds[dd][j], 0u),
                            (unsigned)(MAXD - 1));
                float2 dyz = s_dyz[dd][j];
                float2 ev = s_emb[d];
                mm0 = fmaxf(mm0, dyz.x + ev.x);
                mm1 = fmaxf(mm1, dyz.y + ev.y);
            }
            m0 = fmaxf(m0, cr.y + mm0);
            m1 = fmaxf(m1, cr.z + mm1);
            for (int j = 32; j < nd; j++) {
                float4 dr = g_dlist[de * CAP + j];
                int d = min(__usad((unsigned)cs, (unsigned)__float_as_int(dr.x), 0u),
                            (unsigned)(MAXD - 1));
                float2 ev = s_emb[d];
                m0 = fmaxf(m0, cr.y + dr.y + ev.x);
                m1 = fmaxf(m1, cr.z + dr.z + ev.y);
            }
        }
        #pragma unroll
        for (int off = 16; off > 0; off >>= 1) {
            m0 = fmaxf(m0, __shfl_xor_sync(0xffffffffu, m0, off));
            m1 = fmaxf(m1, __shfl_xor_sync(0xffffffffu, m1, off));
        }
        if (lane == 0) {
            float x0 = m0 + bs0, x1 = m1 + bs1;
            float mx = fmaxf(x0, x1);
            float e0 = expf(x0 - mx), e1 = expf(x1 - mx);
            float inv = 1.f / (e0 + e1);
            out[(ce * NENT + de) * 2 + 0] = e0 * inv;
            out[(ce * NENT + de) * 2 + 1] = e1 * inv;
        }
    }

    // ticket: last block re-zeroes g_cnt (+g_done) for next replay
    __threadfence();
    __syncthreads();
    if (tid == 0) {
        int old = atomicAdd(&g_done, 1);
        if (old == NENT * 8 - 1) {
            #pragma unroll 1
            for (int i = 0; i < 2 * NENT; i++) g_cnt[i] = 0;
            g_done = 0;
            __threadfence();
        }
    }
}

// ---------------- launch ----------------
extern "C" void kernel_launch(void* const* d_in, const int* in_sizes, int n_in,
                              void* d_out, int out_size) {
    const float* h    = (const float*)d_in[0];
    const void*  csp  = d_in[1];
    const void*  cent = d_in[2];
    const void*  dsp  = d_in[3];
    const void*  dent = d_in[4];
    const float* Wc   = (const float*)d_in[5];
    const float* bc   = (const float*)d_in[6];
    const float* Wd   = (const float*)d_in[7];
    const float* bd   = (const float*)d_in[8];
    const float* Wemb = (const float*)d_in[9];
    const float* Ws   = (const float*)d_in[10];
    const float* bs   = (const float*)d_in[11];
    float* out = (float*)d_out;

    k_mention<<<2 * MM / BMM, NTH>>>(h, csp, cent, dsp, dent, Wc, bc, Wd, bd, Ws, Wemb);
    k_pair<<<dim3(NENT, 8), 256>>>(bs, out);
}